// round 16
// baseline (speedup 1.0000x reference)
#include <cuda_runtime.h>
#include <cuda_bf16.h>
#include <math.h>
#include <stdint.h>

// ---------------- problem constants ----------------
#define BATCH 32
#define DEPTH 11
#define NNODES 2047
#define MD 300
#define KDIM 300
#define KPAD 320
#define KT 10                 // KPAD / 32 k-stages
#define LEAF_BASE 1023
#define TOTAL_ROWS (BATCH * NNODES)   // 65504
#define MAXSUM (BATCH * 512)

// padded N strides
#define NPB 1280              // interleaved Wx: 4*300 -> 1280
#define NP_H 1024             // blocked [ih|oh|uh] 900 -> 1024
#define NP_F 384              // Wfh 300 -> 384

// ---------------- GEMM tile ----------------
#define BM 128
#define BN 128
#define OFF_AHI 0
#define OFF_ALO 10240
#define OFF_BHI 20480
#define OFF_BLO 29184
#define STAGE_B 37888
#define SMEM_G (3 * STAGE_B)   // 113664 -> 2 CTAs/SM if regs <= 128

typedef __nv_bfloat16 bf16;

// ---------------- device scratch ----------------
__device__ float g_gates_x[(size_t)TOTAL_ROWS * 1200]; // interleaved n=4j+g, +bx
__device__ float g_c[(size_t)TOTAL_ROWS * MD];
__device__ float g_iou[(size_t)MAXSUM * 900];          // blocked [ih|oh|uh]
__device__ float g_f[(size_t)(2 * MAXSUM) * 300];
__device__ __align__(16) float g_bx4[NPB];
__device__ __align__(16) float g_bh4[NPB];

__device__ __align__(16) bf16 g_embh[(size_t)TOTAL_ROWS * KPAD];
__device__ __align__(16) bf16 g_embl[(size_t)TOTAL_ROWS * KPAD];
__device__ __align__(16) bf16 g_hh[(size_t)TOTAL_ROWS * KPAD];
__device__ __align__(16) bf16 g_hl[(size_t)TOTAL_ROWS * KPAD];
__device__ __align__(16) bf16 g_sumh[(size_t)MAXSUM * KPAD];
__device__ __align__(16) bf16 g_suml[(size_t)MAXSUM * KPAD];
__device__ __align__(16) bf16 g_Wxh[(size_t)KPAD * NPB];
__device__ __align__(16) bf16 g_Wxl[(size_t)KPAD * NPB];
__device__ __align__(16) bf16 g_Whh[(size_t)KPAD * NP_H];
__device__ __align__(16) bf16 g_Whl[(size_t)KPAD * NP_H];
__device__ __align__(16) bf16 g_Wfh[(size_t)KPAD * NP_F];
__device__ __align__(16) bf16 g_Wfl[(size_t)KPAD * NP_F];

__device__ __forceinline__ float sigmoidf(float x) {
    return 1.0f / (1.0f + expf(-x));
}
__device__ __forceinline__ void split_bf16(float v, bf16& hi, bf16& lo) {
    hi = __float2bfloat16(v);
    lo = __float2bfloat16(v - __bfloat162float(hi));
}

// ---------------- ptx helpers ----------------
__device__ __forceinline__ uint32_t smem_u32(const void* p) {
    uint32_t a;
    asm("{ .reg .u64 t; cvta.to.shared.u64 t, %1; cvt.u32.u64 %0, t; }" : "=r"(a) : "l"(p));
    return a;
}
__device__ __forceinline__ void cp16(uint32_t dst, const void* src, int sz) {
    asm volatile("cp.async.cg.shared.global [%0], [%1], 16, %2;"
                 :: "r"(dst), "l"(src), "r"(sz));
}
__device__ __forceinline__ void cp_commit() { asm volatile("cp.async.commit_group;"); }
__device__ __forceinline__ void ldsm4(unsigned* r, uint32_t a) {
    asm volatile("ldmatrix.sync.aligned.m8n8.x4.shared.b16 {%0,%1,%2,%3}, [%4];"
                 : "=r"(r[0]), "=r"(r[1]), "=r"(r[2]), "=r"(r[3]) : "r"(a));
}
__device__ __forceinline__ void ldsm4t(unsigned* r, uint32_t a) {
    asm volatile("ldmatrix.sync.aligned.m8n8.x4.trans.shared.b16 {%0,%1,%2,%3}, [%4];"
                 : "=r"(r[0]), "=r"(r[1]), "=r"(r[2]), "=r"(r[3]) : "r"(a));
}
__device__ __forceinline__ void mma16816(float* d, const unsigned* a, const unsigned* b) {
    asm volatile(
        "mma.sync.aligned.m16n8k16.row.col.f32.bf16.bf16.f32 "
        "{%0,%1,%2,%3}, {%4,%5,%6,%7}, {%8,%9}, {%0,%1,%2,%3};"
        : "+f"(d[0]), "+f"(d[1]), "+f"(d[2]), "+f"(d[3])
        : "r"(a[0]), "r"(a[1]), "r"(a[2]), "r"(a[3]), "r"(b[0]), "r"(b[1]));
}

// ---------------- weight packing ----------------
__global__ void pack_kernel(
    const float* __restrict__ Wix, const float* __restrict__ Wfx,
    const float* __restrict__ Wox, const float* __restrict__ Wux,
    const float* __restrict__ Wih, const float* __restrict__ Wfh,
    const float* __restrict__ Woh, const float* __restrict__ Wuh,
    const float* __restrict__ bix, const float* __restrict__ bfx,
    const float* __restrict__ box_, const float* __restrict__ bux,
    const float* __restrict__ bih, const float* __restrict__ bfh,
    const float* __restrict__ boh, const float* __restrict__ buh)
{
    const int i = blockIdx.x * blockDim.x + threadIdx.x;
    if (i < KPAD * NPB) {   // interleaved Wx: n = 4j + g
        const int k = i / NPB, n = i % NPB;
        const int j = n >> 2, g = n & 3;
        float v = 0.0f;
        if (k < KDIM && j < 300) {
            const float* W = (g == 0) ? Wix : (g == 1) ? Wfx : (g == 2) ? Wox : Wux;
            v = W[k * 300 + j];
        }
        split_bf16(v, g_Wxh[i], g_Wxl[i]);
    }
    if (i < KPAD * NP_H) {  // blocked Wh: [ih|oh|uh]
        const int k = i / NP_H, n = i % NP_H;
        float v = 0.0f;
        if (k < KDIM && n < 900) {
            const int g = n / 300, j = n % 300;
            const float* W = (g == 0) ? Wih : (g == 1) ? Woh : Wuh;
            v = W[k * 300 + j];
        }
        split_bf16(v, g_Whh[i], g_Whl[i]);
    }
    if (i < KPAD * NP_F) {
        const int k = i / NP_F, n = i % NP_F;
        const float v = (k < KDIM && n < 300) ? Wfh[k * 300 + n] : 0.0f;
        split_bf16(v, g_Wfh[i], g_Wfl[i]);
    }
    if (i < NPB) {
        const int j = i >> 2, g = i & 3;
        float vb = 0.0f, vh = 0.0f;
        if (j < 300) {
            vb = ((g == 0) ? bix : (g == 1) ? bfx : (g == 2) ? box_ : bux)[j];
            vh = ((g == 0) ? bih : (g == 1) ? bfh : (g == 2) ? boh : buh)[j];
        }
        g_bx4[i] = vb;
        g_bh4[i] = vh;
    }
}

// ---------------- embs -> bf16 hi/lo, padded ----------------
__global__ void convert_embs(const float* __restrict__ embs) {
    const long idx = (long)blockIdx.x * blockDim.x + threadIdx.x;
    if (idx >= (long)TOTAL_ROWS * KPAD) return;
    const long row = idx / KPAD;
    const int k = (int)(idx % KPAD);
    const float v = (k < KDIM) ? embs[row * KDIM + k] : 0.0f;
    split_bf16(v, g_embh[idx], g_embl[idx]);
}

// ---------------- per-level child-sum + split ----------------
__global__ void sumsplit_kernel(const float* __restrict__ h, int l) {
    const int nl = 1 << l;
    const int Mh = BATCH << l;
    const int total = Mh * MD;
    const int idx = blockIdx.x * blockDim.x + threadIdx.x;
    if (idx >= total) return;
    const int j = idx % MD;
    const int r = idx / MD;
    const int b = r >> l;
    const int t = r & (nl - 1);
    const int node = (nl - 1) + t;
    const size_t c1 = ((size_t)b * NNODES + 2 * node + 1) * MD;
    const float s = h[c1 + j] + h[c1 + MD + j];
    split_bf16(s, g_sumh[(size_t)r * KPAD + j], g_suml[(size_t)r * KPAD + j]);
}

// ---------------- bf16x3 HMMA GEMM ----------------
// amode 0: A row = grow * KPAD (bf16 hi/lo arrays)
// amode 2: A row = h-split row of child(1|2) at level lvl (stacked 2*Mh)
// epi 0: plain C store (no bias)
// epi 1: big-projection fused epilogue (leaf -> c,h,splits; internal -> gates_x+bx)
__global__ __launch_bounds__(256, 2) void gemm_mma(
    const bf16* __restrict__ Ah, const bf16* __restrict__ Al,
    const bf16* __restrict__ Bh, const bf16* __restrict__ Bl,
    float* __restrict__ C, float* __restrict__ hbuf,
    int M, int N, int NP, int ldc, int amode, int lvl, int epi)
{
    extern __shared__ __align__(128) char smem[];
    const uint32_t sbase = smem_u32(smem);
    const int tid = threadIdx.x;
    const int lane = tid & 31;
    const int wid = tid >> 5;
    const int wm = wid & 3;
    const int wn = wid >> 2;
    const int m_base = blockIdx.y * BM;
    const int n_base = blockIdx.x * BN;

    // ---- A staging offsets ----
    const int c4 = tid & 3;
    const int ar0 = tid >> 2;
    size_t aoff[2]; int asz[2];
#pragma unroll
    for (int i = 0; i < 2; i++) {
        const int grow = m_base + ar0 + i * 64;
        const bool ok = grow < M;
        size_t off = 0;
        if (ok) {
            if (amode == 0) {
                off = (size_t)grow * KPAD;
            } else {
                const int nl = 1 << lvl;
                const int Mh = BATCH << lvl;
                int rr = grow, sel = 0;
                if (grow >= Mh) { sel = 1; rr -= Mh; }
                const int b = rr >> lvl;
                const int t = rr & (nl - 1);
                const int node = (nl - 1) + t;
                off = ((size_t)b * NNODES + 2 * node + 1 + sel) * KPAD;
            }
        }
        aoff[i] = off; asz[i] = ok ? 16 : 0;
    }
    const int cb = tid & 15;
    const int br0 = tid >> 4;
    const int bn0 = n_base + cb * 8;

    // ---- ldmatrix lane addresses ----
    const uint32_t a_lane = (uint32_t)((lane & 15) * 80 + (lane >> 4) * 16);
    const int jj = lane >> 3, r8 = lane & 7;
    const uint32_t b_lane = (uint32_t)(((jj & 1) * 8 + r8) * 272 + (jj >> 1) * 16);

    float acc[2][8][4];
#pragma unroll
    for (int a = 0; a < 2; a++)
#pragma unroll
        for (int b = 0; b < 8; b++)
#pragma unroll
            for (int c = 0; c < 4; c++) acc[a][b][c] = 0.0f;

    auto stage = [&](int t, int buf) {
        const uint32_t sb = sbase + buf * STAGE_B;
        const int k0 = t * 32;
#pragma unroll
        for (int i = 0; i < 2; i++) {
            const int row = ar0 + i * 64;
            const size_t so = aoff[i] + k0 + c4 * 8;
            const uint32_t d = sb + row * 80 + c4 * 16;
            cp16(d + OFF_AHI, Ah + so, asz[i]);
            cp16(d + OFF_ALO, Al + so, asz[i]);
        }
#pragma unroll
        for (int i = 0; i < 2; i++) {
            const int kr = br0 + i * 16;
            const size_t so = (size_t)(k0 + kr) * NP + bn0;
            const uint32_t d = sb + kr * 272 + cb * 16;
            cp16(d + OFF_BHI, Bh + so, 16);
            cp16(d + OFF_BLO, Bl + so, 16);
        }
    };

    stage(0, 0); cp_commit();
    stage(1, 1); cp_commit();

    for (int t = 0; t < KT; ++t) {
        asm volatile("cp.async.wait_group 1;" ::: "memory");
        __syncthreads();
        if (t + 2 < KT) stage(t + 2, (t + 2) % 3);
        cp_commit();

        const uint32_t sb = sbase + (t % 3) * STAGE_B;
#pragma unroll
        for (int k16 = 0; k16 < 2; k16++) {
            unsigned ah[2][4], al[2][4];
#pragma unroll
            for (int tm = 0; tm < 2; tm++) {
                const uint32_t ad = sb + (wm * 32 + tm * 16) * 80 + k16 * 32 + a_lane;
                ldsm4(ah[tm], ad + OFF_AHI);
                ldsm4(al[tm], ad + OFF_ALO);
            }
#pragma unroll
            for (int p = 0; p < 4; p++) {
                const uint32_t bd = sb + (uint32_t)(k16 * 16 * 272) +
                                    (uint32_t)((wn * 64 + p * 16) * 2) + b_lane;
                unsigned rh[4], rl[4];
                ldsm4t(rh, bd + OFF_BHI);
                ldsm4t(rl, bd + OFF_BLO);
#pragma unroll
                for (int tm = 0; tm < 2; tm++) {
                    mma16816(acc[tm][2 * p],     ah[tm], &rh[0]);
                    mma16816(acc[tm][2 * p],     ah[tm], &rl[0]);
                    mma16816(acc[tm][2 * p],     al[tm], &rh[0]);
                    mma16816(acc[tm][2 * p + 1], ah[tm], &rh[2]);
                    mma16816(acc[tm][2 * p + 1], ah[tm], &rl[2]);
                    mma16816(acc[tm][2 * p + 1], al[tm], &rh[2]);
                }
            }
        }
    }

    // ---- epilogue ----
    const int mrow = lane >> 2;
    const int npair = (lane & 3) * 2;

    if (epi == 0) {
#pragma unroll
        for (int tm = 0; tm < 2; tm++) {
#pragma unroll
            for (int half = 0; half < 2; half++) {
                const int gm = m_base + wm * 32 + tm * 16 + half * 8 + mrow;
                if (gm >= M) continue;
                float* crow = C + (size_t)gm * ldc;
#pragma unroll
                for (int tn = 0; tn < 8; tn++) {
                    const int gn = n_base + wn * 64 + tn * 8 + npair;
                    if (gn < N) {
                        crow[gn]     = acc[tm][tn][half * 2];
                        crow[gn + 1] = acc[tm][tn][half * 2 + 1];
                    }
                }
            }
        }
    } else {
        // big projection: interleaved gates (n = 4j + g), N = 1200 real
#pragma unroll
        for (int tm = 0; tm < 2; tm++) {
#pragma unroll
            for (int half = 0; half < 2; half++) {
                const int gm = m_base + wm * 32 + tm * 16 + half * 8 + mrow;
                const bool rowok = (gm < M);
                const int node = rowok ? (gm % NNODES) : 0;
                const bool leaf = rowok && (node >= LEAF_BASE);
#pragma unroll
                for (int tn = 0; tn < 8; tn++) {
                    const int n = n_base + wn * 64 + tn * 8 + npair;
                    const float v0 = acc[tm][tn][half * 2];
                    const float v1 = acc[tm][tn][half * 2 + 1];
                    const float p0 = __shfl_xor_sync(0xffffffffu, v0, 1);
                    const float p1 = __shfl_xor_sync(0xffffffffu, v1, 1);
                    if (!rowok || n >= 1200) continue;
                    if (!leaf) {
                        float2 o2;
                        o2.x = v0 + g_bx4[n];
                        o2.y = v1 + g_bx4[n + 1];
                        *(float2*)(g_gates_x + (size_t)gm * 1200 + n) = o2;
                    } else {
                        float ir, orr, ur;
                        if ((lane & 1) == 0) { ir = v0; orr = p0; ur = p1; }
                        else                 { ir = p0; orr = v0; ur = v1; }
                        const int j = n >> 2;
                        const float4 bx = *(const float4*)(g_bx4 + 4 * j);
                        const float4 bh = *(const float4*)(g_bh4 + 4 * j);
                        const float iv = sigmoidf(ir + bx.x + bh.x);
                        const float ov = sigmoidf(orr + bx.z + bh.z);
                        const float uv = tanhf(ur + bx.w + bh.w);
                        const float cv = iv * uv;
                        if ((lane & 1) == 0) {
                            g_c[(size_t)gm * MD + j] = cv;
                        } else {
                            const float hv = ov * tanhf(cv);
                            hbuf[(size_t)gm * MD + j] = hv;
                            split_bf16(hv, g_hh[(size_t)gm * KPAD + j],
                                           g_hl[(size_t)gm * KPAD + j]);
                        }
                    }
                }
            }
        }
    }
}

// ---------------- pointwise: internal level (+ h split) ----------------
__global__ void level_kernel(float* __restrict__ h, int l,
                             const float* __restrict__ bih,
                             const float* __restrict__ boh,
                             const float* __restrict__ buh,
                             const float* __restrict__ bfh)
{
    const int nl = 1 << l;
    const int Mh = BATCH << l;
    const int total = Mh * MD;
    const int idx = blockIdx.x * blockDim.x + threadIdx.x;
    if (idx >= total) return;
    const int j = idx % MD;
    const int r = idx / MD;
    const int t = r & (nl - 1);
    const int b = r >> l;
    const int node = (nl - 1) + t;
    const size_t rowx = (size_t)b * NNODES + node;
    const float4 gx = *(const float4*)(g_gates_x + rowx * 1200 + 4 * j); // i,f,o,u (+bx)
    const float* gio = g_iou + (size_t)r * 900;

    const float i  = sigmoidf(gx.x + gio[j]       + bih[j]);
    const float o  = sigmoidf(gx.z + gio[300 + j] + boh[j]);
    const float u  = tanhf   (gx.w + gio[600 + j] + buh[j]);
    const float f1 = sigmoidf(gx.y + g_f[(size_t)r * 300 + j] + bfh[j]);
    const float f2 = sigmoidf(gx.y + g_f[(size_t)(Mh + r) * 300 + j] + bfh[j]);

    const size_t row1 = (size_t)b * NNODES + 2 * node + 1;
    const float cn = i * u + f1 * g_c[row1 * MD + j] + f2 * g_c[(row1 + 1) * MD + j];
    const float hv = o * tanhf(cn);
    g_c[rowx * MD + j] = cn;
    h[rowx * MD + j] = hv;
    split_bf16(hv, g_hh[rowx * KPAD + j], g_hl[rowx * KPAD + j]);
}

// ---------------- host launch ----------------
extern "C" void kernel_launch(void* const* d_in, const int* in_sizes, int n_in,
                              void* d_out, int out_size)
{
    const float* embs = (const float*)d_in[0];
    const float* Wix = (const float*)d_in[1];
    const float* bix = (const float*)d_in[2];
    const float* Wih = (const float*)d_in[3];
    const float* bih = (const float*)d_in[4];
    const float* Wfx = (const float*)d_in[5];
    const float* bfx = (const float*)d_in[6];
    const float* Wfh = (const float*)d_in[7];
    const float* bfh = (const float*)d_in[8];
    const float* Wox = (const float*)d_in[9];
    const float* box_ = (const float*)d_in[10];
    const float* Woh = (const float*)d_in[11];
    const float* boh = (const float*)d_in[12];
    const float* Wux = (const float*)d_in[13];
    const float* bux = (const float*)d_in[14];
    const float* Wuh = (const float*)d_in[15];
    const float* buh = (const float*)d_in[16];
    float* h = (float*)d_out;

    cudaFuncSetAttribute(gemm_mma,
                         cudaFuncAttributeMaxDynamicSharedMemorySize, SMEM_G);

    float *iou_p, *f_p;
    bf16 *embh_p, *embl_p, *hh_p, *hl_p, *sumh_p, *suml_p;
    bf16 *Wxh_p, *Wxl_p, *Whh_p, *Whl_p, *Wfh_p, *Wfl_p;
    cudaGetSymbolAddress((void**)&iou_p, g_iou);
    cudaGetSymbolAddress((void**)&f_p, g_f);
    cudaGetSymbolAddress((void**)&embh_p, g_embh);
    cudaGetSymbolAddress((void**)&embl_p, g_embl);
    cudaGetSymbolAddress((void**)&hh_p, g_hh);
    cudaGetSymbolAddress((void**)&hl_p, g_hl);
    cudaGetSymbolAddress((void**)&sumh_p, g_sumh);
    cudaGetSymbolAddress((void**)&suml_p, g_suml);
    cudaGetSymbolAddress((void**)&Wxh_p, g_Wxh);
    cudaGetSymbolAddress((void**)&Wxl_p, g_Wxl);
    cudaGetSymbolAddress((void**)&Whh_p, g_Whh);
    cudaGetSymbolAddress((void**)&Whl_p, g_Whl);
    cudaGetSymbolAddress((void**)&Wfh_p, g_Wfh);
    cudaGetSymbolAddress((void**)&Wfl_p, g_Wfl);

    // 1. pack weights + biases
    pack_kernel<<<(KPAD * NPB + 255) / 256, 256>>>(
        Wix, Wfx, Wox, Wux, Wih, Wfh, Woh, Wuh,
        bix, bfx, box_, bux, bih, bfh, boh, buh);

    // 2. convert embeddings to bf16 hi/lo
    {
        const long total = (long)TOTAL_ROWS * KPAD;
        convert_embs<<<(int)((total + 255) / 256), 256>>>(embs);
    }

    // 3. big projection + fused leaf / interleaved gate store
    {
        dim3 grid(NPB / BN, (TOTAL_ROWS + BM - 1) / BM);   // (10, 512)
        gemm_mma<<<grid, 256, SMEM_G>>>(embh_p, embl_p, Wxh_p, Wxl_p,
                                        nullptr, h,
                                        TOTAL_ROWS, 1200, NPB, 0,
                                        /*amode=*/0, 0, /*epi=*/1);
    }

    // 4. tree recursion
    for (int l = DEPTH - 2; l >= 0; --l) {
        const int Mh = BATCH << l;
        sumsplit_kernel<<<(Mh * MD + 255) / 256, 256>>>(h, l);
        {
            dim3 grid((900 + BN - 1) / BN, (Mh + BM - 1) / BM);
            gemm_mma<<<grid, 256, SMEM_G>>>(sumh_p, suml_p, Whh_p, Whl_p,
                                            iou_p, nullptr,
                                            Mh, 900, NP_H, 900,
                                            /*amode=*/0, 0, /*epi=*/0);
        }
        {
            dim3 grid((300 + BN - 1) / BN, (2 * Mh + BM - 1) / BM);
            gemm_mma<<<grid, 256, SMEM_G>>>(hh_p, hl_p, Wfh_p, Wfl_p,
                                            f_p, nullptr,
                                            2 * Mh, 300, NP_F, 300,
                                            /*amode=*/2, l, /*epi=*/0);
        }
        level_kernel<<<(Mh * MD + 255) / 256, 256>>>(h, l, bih, boh, buh, bfh);
    }
}

// round 17
// speedup vs baseline: 1.0034x; 1.0034x over previous
#include <cuda_runtime.h>
#include <cuda_bf16.h>
#include <math.h>
#include <stdint.h>

// ---------------- problem constants ----------------
#define BATCH 32
#define DEPTH 11
#define NNODES 2047
#define MD 300
#define KDIM 300
#define KPAD 320
#define KT 10                 // KPAD / 32 k-stages
#define LEAF_BASE 1023
#define TOTAL_ROWS (BATCH * NNODES)   // 65504
#define MAXSUM (BATCH * 512)

// padded N strides
#define NPB 1280              // interleaved Wx: 4*300 -> 1280
#define NP_H 1024             // blocked [ih|oh|uh] 900 -> 1024
#define NP_F 384              // Wfh 300 -> 384

// ---------------- GEMM tile ----------------
#define BM 128
#define BN 128
#define OFF_AHI 0
#define OFF_ALO 10240
#define OFF_BHI 20480
#define OFF_BLO 29184
#define STAGE_B 37888
#define SMEM_G (3 * STAGE_B)   // 113664 -> 2 CTAs/SM if regs <= 128

typedef __nv_bfloat16 bf16;

// ---------------- device scratch ----------------
__device__ float g_gates_x[(size_t)TOTAL_ROWS * 1200]; // interleaved n=4j+g, +bx
__device__ float g_c[(size_t)TOTAL_ROWS * MD];
__device__ float g_iou[(size_t)MAXSUM * 900];          // blocked [ih|oh|uh]
__device__ float g_f[(size_t)(2 * MAXSUM) * 300];
__device__ __align__(16) float g_bx4[NPB];
__device__ __align__(16) float g_bh4[NPB];

__device__ __align__(16) bf16 g_embh[(size_t)TOTAL_ROWS * KPAD];
__device__ __align__(16) bf16 g_embl[(size_t)TOTAL_ROWS * KPAD];
__device__ __align__(16) bf16 g_hh[(size_t)TOTAL_ROWS * KPAD];
__device__ __align__(16) bf16 g_hl[(size_t)TOTAL_ROWS * KPAD];
__device__ __align__(16) bf16 g_sumh[(size_t)MAXSUM * KPAD];
__device__ __align__(16) bf16 g_suml[(size_t)MAXSUM * KPAD];
__device__ __align__(16) bf16 g_Wxh[(size_t)KPAD * NPB];
__device__ __align__(16) bf16 g_Wxl[(size_t)KPAD * NPB];
__device__ __align__(16) bf16 g_Whh[(size_t)KPAD * NP_H];
__device__ __align__(16) bf16 g_Whl[(size_t)KPAD * NP_H];
__device__ __align__(16) bf16 g_Wfh[(size_t)KPAD * NP_F];
__device__ __align__(16) bf16 g_Wfl[(size_t)KPAD * NP_F];

__device__ __forceinline__ float sigmoidf(float x) {
    return 1.0f / (1.0f + expf(-x));
}
__device__ __forceinline__ void split_bf16(float v, bf16& hi, bf16& lo) {
    hi = __float2bfloat16(v);
    lo = __float2bfloat16(v - __bfloat162float(hi));
}

// ---------------- ptx helpers ----------------
__device__ __forceinline__ uint32_t smem_u32(const void* p) {
    uint32_t a;
    asm("{ .reg .u64 t; cvta.to.shared.u64 t, %1; cvt.u32.u64 %0, t; }" : "=r"(a) : "l"(p));
    return a;
}
__device__ __forceinline__ void cp16(uint32_t dst, const void* src, int sz) {
    asm volatile("cp.async.cg.shared.global [%0], [%1], 16, %2;"
                 :: "r"(dst), "l"(src), "r"(sz));
}
__device__ __forceinline__ void cp_commit() { asm volatile("cp.async.commit_group;"); }
__device__ __forceinline__ void ldsm4(unsigned* r, uint32_t a) {
    asm volatile("ldmatrix.sync.aligned.m8n8.x4.shared.b16 {%0,%1,%2,%3}, [%4];"
                 : "=r"(r[0]), "=r"(r[1]), "=r"(r[2]), "=r"(r[3]) : "r"(a));
}
__device__ __forceinline__ void ldsm4t(unsigned* r, uint32_t a) {
    asm volatile("ldmatrix.sync.aligned.m8n8.x4.trans.shared.b16 {%0,%1,%2,%3}, [%4];"
                 : "=r"(r[0]), "=r"(r[1]), "=r"(r[2]), "=r"(r[3]) : "r"(a));
}
__device__ __forceinline__ void mma16816(float* d, const unsigned* a, const unsigned* b) {
    asm volatile(
        "mma.sync.aligned.m16n8k16.row.col.f32.bf16.bf16.f32 "
        "{%0,%1,%2,%3}, {%4,%5,%6,%7}, {%8,%9}, {%0,%1,%2,%3};"
        : "+f"(d[0]), "+f"(d[1]), "+f"(d[2]), "+f"(d[3])
        : "r"(a[0]), "r"(a[1]), "r"(a[2]), "r"(a[3]), "r"(b[0]), "r"(b[1]));
}

// ---------------- weight packing ----------------
__global__ void pack_kernel(
    const float* __restrict__ Wix, const float* __restrict__ Wfx,
    const float* __restrict__ Wox, const float* __restrict__ Wux,
    const float* __restrict__ Wih, const float* __restrict__ Wfh,
    const float* __restrict__ Woh, const float* __restrict__ Wuh,
    const float* __restrict__ bix, const float* __restrict__ bfx,
    const float* __restrict__ box_, const float* __restrict__ bux,
    const float* __restrict__ bih, const float* __restrict__ bfh,
    const float* __restrict__ boh, const float* __restrict__ buh)
{
    const int i = blockIdx.x * blockDim.x + threadIdx.x;
    if (i < KPAD * NPB) {   // interleaved Wx: n = 4j + g
        const int k = i / NPB, n = i % NPB;
        const int j = n >> 2, g = n & 3;
        float v = 0.0f;
        if (k < KDIM && j < 300) {
            const float* W = (g == 0) ? Wix : (g == 1) ? Wfx : (g == 2) ? Wox : Wux;
            v = W[k * 300 + j];
        }
        split_bf16(v, g_Wxh[i], g_Wxl[i]);
    }
    if (i < KPAD * NP_H) {  // blocked Wh: [ih|oh|uh]
        const int k = i / NP_H, n = i % NP_H;
        float v = 0.0f;
        if (k < KDIM && n < 900) {
            const int g = n / 300, j = n % 300;
            const float* W = (g == 0) ? Wih : (g == 1) ? Woh : Wuh;
            v = W[k * 300 + j];
        }
        split_bf16(v, g_Whh[i], g_Whl[i]);
    }
    if (i < KPAD * NP_F) {
        const int k = i / NP_F, n = i % NP_F;
        const float v = (k < KDIM && n < 300) ? Wfh[k * 300 + n] : 0.0f;
        split_bf16(v, g_Wfh[i], g_Wfl[i]);
    }
    if (i < NPB) {
        const int j = i >> 2, g = i & 3;
        float vb = 0.0f, vh = 0.0f;
        if (j < 300) {
            vb = ((g == 0) ? bix : (g == 1) ? bfx : (g == 2) ? box_ : bux)[j];
            vh = ((g == 0) ? bih : (g == 1) ? bfh : (g == 2) ? boh : buh)[j];
        }
        g_bx4[i] = vb;
        g_bh4[i] = vh;
    }
}

// ---------------- embs -> bf16 hi/lo, padded ----------------
__global__ void convert_embs(const float* __restrict__ embs) {
    const long idx = (long)blockIdx.x * blockDim.x + threadIdx.x;
    if (idx >= (long)TOTAL_ROWS * KPAD) return;
    const long row = idx / KPAD;
    const int k = (int)(idx % KPAD);
    const float v = (k < KDIM) ? embs[row * KDIM + k] : 0.0f;
    split_bf16(v, g_embh[idx], g_embl[idx]);
}

// ---------------- per-level child-sum + split ----------------
__global__ void sumsplit_kernel(const float* __restrict__ h, int l) {
    const int nl = 1 << l;
    const int Mh = BATCH << l;
    const int total = Mh * MD;
    const int idx = blockIdx.x * blockDim.x + threadIdx.x;
    if (idx >= total) return;
    const int j = idx % MD;
    const int r = idx / MD;
    const int b = r >> l;
    const int t = r & (nl - 1);
    const int node = (nl - 1) + t;
    const size_t c1 = ((size_t)b * NNODES + 2 * node + 1) * MD;
    const float s = h[c1 + j] + h[c1 + MD + j];
    split_bf16(s, g_sumh[(size_t)r * KPAD + j], g_suml[(size_t)r * KPAD + j]);
}

// ---------------- bf16x3 HMMA GEMM ----------------
// amode 0: A row = grow * KPAD (bf16 hi/lo arrays)
// amode 2: A row = h-split row of child(1|2) at level lvl (stacked 2*Mh)
// epi 0: plain C store (no bias)
// epi 1: big-projection fused epilogue (leaf -> c,h,splits; internal -> gates_x+bx)
__global__ __launch_bounds__(256, 2) void gemm_mma(
    const bf16* __restrict__ Ah, const bf16* __restrict__ Al,
    const bf16* __restrict__ Bh, const bf16* __restrict__ Bl,
    float* __restrict__ C, float* __restrict__ hbuf,
    int M, int N, int NP, int ldc, int amode, int lvl, int epi)
{
    extern __shared__ __align__(128) char smem[];
    const uint32_t sbase = smem_u32(smem);
    const int tid = threadIdx.x;
    const int lane = tid & 31;
    const int wid = tid >> 5;
    const int wm = wid & 3;
    const int wn = wid >> 2;
    const int m_base = blockIdx.y * BM;
    const int n_base = blockIdx.x * BN;

    // ---- A staging offsets ----
    const int c4 = tid & 3;
    const int ar0 = tid >> 2;
    size_t aoff[2]; int asz[2];
#pragma unroll
    for (int i = 0; i < 2; i++) {
        const int grow = m_base + ar0 + i * 64;
        const bool ok = grow < M;
        size_t off = 0;
        if (ok) {
            if (amode == 0) {
                off = (size_t)grow * KPAD;
            } else {
                const int nl = 1 << lvl;
                const int Mh = BATCH << lvl;
                int rr = grow, sel = 0;
                if (grow >= Mh) { sel = 1; rr -= Mh; }
                const int b = rr >> lvl;
                const int t = rr & (nl - 1);
                const int node = (nl - 1) + t;
                off = ((size_t)b * NNODES + 2 * node + 1 + sel) * KPAD;
            }
        }
        aoff[i] = off; asz[i] = ok ? 16 : 0;
    }
    const int cb = tid & 15;
    const int br0 = tid >> 4;
    const int bn0 = n_base + cb * 8;

    // ---- ldmatrix lane addresses ----
    const uint32_t a_lane = (uint32_t)((lane & 15) * 80 + (lane >> 4) * 16);
    const int jj = lane >> 3, r8 = lane & 7;
    const uint32_t b_lane = (uint32_t)(((jj & 1) * 8 + r8) * 272 + (jj >> 1) * 16);

    float acc[2][8][4];
#pragma unroll
    for (int a = 0; a < 2; a++)
#pragma unroll
        for (int b = 0; b < 8; b++)
#pragma unroll
            for (int c = 0; c < 4; c++) acc[a][b][c] = 0.0f;

    auto stage = [&](int t, int buf) {
        const uint32_t sb = sbase + buf * STAGE_B;
        const int k0 = t * 32;
#pragma unroll
        for (int i = 0; i < 2; i++) {
            const int row = ar0 + i * 64;
            const size_t so = aoff[i] + k0 + c4 * 8;
            const uint32_t d = sb + row * 80 + c4 * 16;
            cp16(d + OFF_AHI, Ah + so, asz[i]);
            cp16(d + OFF_ALO, Al + so, asz[i]);
        }
#pragma unroll
        for (int i = 0; i < 2; i++) {
            const int kr = br0 + i * 16;
            const size_t so = (size_t)(k0 + kr) * NP + bn0;
            const uint32_t d = sb + kr * 272 + cb * 16;
            cp16(d + OFF_BHI, Bh + so, 16);
            cp16(d + OFF_BLO, Bl + so, 16);
        }
    };

    stage(0, 0); cp_commit();
    stage(1, 1); cp_commit();

    for (int t = 0; t < KT; ++t) {
        asm volatile("cp.async.wait_group 1;" ::: "memory");
        __syncthreads();
        if (t + 2 < KT) stage(t + 2, (t + 2) % 3);
        cp_commit();

        const uint32_t sb = sbase + (t % 3) * STAGE_B;
#pragma unroll
        for (int k16 = 0; k16 < 2; k16++) {
            unsigned ah[2][4], al[2][4];
#pragma unroll
            for (int tm = 0; tm < 2; tm++) {
                const uint32_t ad = sb + (wm * 32 + tm * 16) * 80 + k16 * 32 + a_lane;
                ldsm4(ah[tm], ad + OFF_AHI);
                ldsm4(al[tm], ad + OFF_ALO);
            }
#pragma unroll
            for (int p = 0; p < 4; p++) {
                const uint32_t bd = sb + (uint32_t)(k16 * 16 * 272) +
                                    (uint32_t)((wn * 64 + p * 16) * 2) + b_lane;
                unsigned rh[4], rl[4];
                ldsm4t(rh, bd + OFF_BHI);
                ldsm4t(rl, bd + OFF_BLO);
#pragma unroll
                for (int tm = 0; tm < 2; tm++) {
                    mma16816(acc[tm][2 * p],     ah[tm], &rh[0]);
                    mma16816(acc[tm][2 * p],     ah[tm], &rl[0]);
                    mma16816(acc[tm][2 * p],     al[tm], &rh[0]);
                    mma16816(acc[tm][2 * p + 1], ah[tm], &rh[2]);
                    mma16816(acc[tm][2 * p + 1], ah[tm], &rl[2]);
                    mma16816(acc[tm][2 * p + 1], al[tm], &rh[2]);
                }
            }
        }
    }

    // ---- epilogue ----
    const int mrow = lane >> 2;
    const int npair = (lane & 3) * 2;

    if (epi == 0) {
#pragma unroll
        for (int tm = 0; tm < 2; tm++) {
#pragma unroll
            for (int half = 0; half < 2; half++) {
                const int gm = m_base + wm * 32 + tm * 16 + half * 8 + mrow;
                if (gm >= M) continue;
                float* crow = C + (size_t)gm * ldc;
#pragma unroll
                for (int tn = 0; tn < 8; tn++) {
                    const int gn = n_base + wn * 64 + tn * 8 + npair;
                    if (gn < N) {
                        crow[gn]     = acc[tm][tn][half * 2];
                        crow[gn + 1] = acc[tm][tn][half * 2 + 1];
                    }
                }
            }
        }
    } else {
        // big projection: interleaved gates (n = 4j + g), N = 1200 real
#pragma unroll
        for (int tm = 0; tm < 2; tm++) {
#pragma unroll
            for (int half = 0; half < 2; half++) {
                const int gm = m_base + wm * 32 + tm * 16 + half * 8 + mrow;
                const bool rowok = (gm < M);
                const int node = rowok ? (gm % NNODES) : 0;
                const bool leaf = rowok && (node >= LEAF_BASE);
#pragma unroll
                for (int tn = 0; tn < 8; tn++) {
                    const int n = n_base + wn * 64 + tn * 8 + npair;
                    const float v0 = acc[tm][tn][half * 2];
                    const float v1 = acc[tm][tn][half * 2 + 1];
                    const float p0 = __shfl_xor_sync(0xffffffffu, v0, 1);
                    const float p1 = __shfl_xor_sync(0xffffffffu, v1, 1);
                    if (!rowok || n >= 1200) continue;
                    if (!leaf) {
                        float2 o2;
                        o2.x = v0 + g_bx4[n];
                        o2.y = v1 + g_bx4[n + 1];
                        *(float2*)(g_gates_x + (size_t)gm * 1200 + n) = o2;
                    } else {
                        float ir, orr, ur;
                        if ((lane & 1) == 0) { ir = v0; orr = p0; ur = p1; }
                        else                 { ir = p0; orr = v0; ur = v1; }
                        const int j = n >> 2;
                        const float4 bx = *(const float4*)(g_bx4 + 4 * j);
                        const float4 bh = *(const float4*)(g_bh4 + 4 * j);
                        const float iv = sigmoidf(ir + bx.x + bh.x);
                        const float ov = sigmoidf(orr + bx.z + bh.z);
                        const float uv = tanhf(ur + bx.w + bh.w);
                        const float cv = iv * uv;
                        if ((lane & 1) == 0) {
                            g_c[(size_t)gm * MD + j] = cv;
                        } else {
                            const float hv = ov * tanhf(cv);
                            hbuf[(size_t)gm * MD + j] = hv;
                            split_bf16(hv, g_hh[(size_t)gm * KPAD + j],
                                           g_hl[(size_t)gm * KPAD + j]);
                        }
                    }
                }
            }
        }
    }
}

// ---------------- pointwise: internal level (+ h split) ----------------
__global__ void level_kernel(float* __restrict__ h, int l,
                             const float* __restrict__ bih,
                             const float* __restrict__ boh,
                             const float* __restrict__ buh,
                             const float* __restrict__ bfh)
{
    const int nl = 1 << l;
    const int Mh = BATCH << l;
    const int total = Mh * MD;
    const int idx = blockIdx.x * blockDim.x + threadIdx.x;
    if (idx >= total) return;
    const int j = idx % MD;
    const int r = idx / MD;
    const int t = r & (nl - 1);
    const int b = r >> l;
    const int node = (nl - 1) + t;
    const size_t rowx = (size_t)b * NNODES + node;
    const float4 gx = *(const float4*)(g_gates_x + rowx * 1200 + 4 * j); // i,f,o,u (+bx)
    const float* gio = g_iou + (size_t)r * 900;

    const float i  = sigmoidf(gx.x + gio[j]       + bih[j]);
    const float o  = sigmoidf(gx.z + gio[300 + j] + boh[j]);
    const float u  = tanhf   (gx.w + gio[600 + j] + buh[j]);
    const float f1 = sigmoidf(gx.y + g_f[(size_t)r * 300 + j] + bfh[j]);
    const float f2 = sigmoidf(gx.y + g_f[(size_t)(Mh + r) * 300 + j] + bfh[j]);

    const size_t row1 = (size_t)b * NNODES + 2 * node + 1;
    const float cn = i * u + f1 * g_c[row1 * MD + j] + f2 * g_c[(row1 + 1) * MD + j];
    const float hv = o * tanhf(cn);
    g_c[rowx * MD + j] = cn;
    h[rowx * MD + j] = hv;
    split_bf16(hv, g_hh[rowx * KPAD + j], g_hl[rowx * KPAD + j]);
}

// ---------------- host launch ----------------
extern "C" void kernel_launch(void* const* d_in, const int* in_sizes, int n_in,
                              void* d_out, int out_size)
{
    const float* embs = (const float*)d_in[0];
    const float* Wix = (const float*)d_in[1];
    const float* bix = (const float*)d_in[2];
    const float* Wih = (const float*)d_in[3];
    const float* bih = (const float*)d_in[4];
    const float* Wfx = (const float*)d_in[5];
    const float* bfx = (const float*)d_in[6];
    const float* Wfh = (const float*)d_in[7];
    const float* bfh = (const float*)d_in[8];
    const float* Wox = (const float*)d_in[9];
    const float* box_ = (const float*)d_in[10];
    const float* Woh = (const float*)d_in[11];
    const float* boh = (const float*)d_in[12];
    const float* Wux = (const float*)d_in[13];
    const float* bux = (const float*)d_in[14];
    const float* Wuh = (const float*)d_in[15];
    const float* buh = (const float*)d_in[16];
    float* h = (float*)d_out;

    cudaFuncSetAttribute(gemm_mma,
                         cudaFuncAttributeMaxDynamicSharedMemorySize, SMEM_G);

    float *iou_p, *f_p;
    bf16 *embh_p, *embl_p, *hh_p, *hl_p, *sumh_p, *suml_p;
    bf16 *Wxh_p, *Wxl_p, *Whh_p, *Whl_p, *Wfh_p, *Wfl_p;
    cudaGetSymbolAddress((void**)&iou_p, g_iou);
    cudaGetSymbolAddress((void**)&f_p, g_f);
    cudaGetSymbolAddress((void**)&embh_p, g_embh);
    cudaGetSymbolAddress((void**)&embl_p, g_embl);
    cudaGetSymbolAddress((void**)&hh_p, g_hh);
    cudaGetSymbolAddress((void**)&hl_p, g_hl);
    cudaGetSymbolAddress((void**)&sumh_p, g_sumh);
    cudaGetSymbolAddress((void**)&suml_p, g_suml);
    cudaGetSymbolAddress((void**)&Wxh_p, g_Wxh);
    cudaGetSymbolAddress((void**)&Wxl_p, g_Wxl);
    cudaGetSymbolAddress((void**)&Whh_p, g_Whh);
    cudaGetSymbolAddress((void**)&Whl_p, g_Whl);
    cudaGetSymbolAddress((void**)&Wfh_p, g_Wfh);
    cudaGetSymbolAddress((void**)&Wfl_p, g_Wfl);

    // 1. pack weights + biases
    pack_kernel<<<(KPAD * NPB + 255) / 256, 256>>>(
        Wix, Wfx, Wox, Wux, Wih, Wfh, Woh, Wuh,
        bix, bfx, box_, bux, bih, bfh, boh, buh);

    // 2. convert embeddings to bf16 hi/lo
    {
        const long total = (long)TOTAL_ROWS * KPAD;
        convert_embs<<<(int)((total + 255) / 256), 256>>>(embs);
    }

    // 3. big projection + fused leaf / interleaved gate store
    {
        dim3 grid(NPB / BN, (TOTAL_ROWS + BM - 1) / BM);   // (10, 512)
        gemm_mma<<<grid, 256, SMEM_G>>>(embh_p, embl_p, Wxh_p, Wxl_p,
                                        nullptr, h,
                                        TOTAL_ROWS, 1200, NPB, 0,
                                        /*amode=*/0, 0, /*epi=*/1);
    }

    // 4. tree recursion
    for (int l = DEPTH - 2; l >= 0; --l) {
        const int Mh = BATCH << l;
        sumsplit_kernel<<<(Mh * MD + 255) / 256, 256>>>(h, l);
        {
            dim3 grid((900 + BN - 1) / BN, (Mh + BM - 1) / BM);
            gemm_mma<<<grid, 256, SMEM_G>>>(sumh_p, suml_p, Whh_p, Whl_p,
                                            iou_p, nullptr,
                                            Mh, 900, NP_H, 900,
                                            /*amode=*/0, 0, /*epi=*/0);
        }
        {
            dim3 grid((300 + BN - 1) / BN, (2 * Mh + BM - 1) / BM);
            gemm_mma<<<grid, 256, SMEM_G>>>(hh_p, hl_p, Wfh_p, Wfl_p,
                                            f_p, nullptr,
                                            2 * Mh, 300, NP_F, 300,
                                            /*amode=*/2, l, /*epi=*/0);
        }
        level_kernel<<<(Mh * MD + 255) / 256, 256>>>(h, l, bih, boh, buh, bfh);
    }
}